// round 15
// baseline (speedup 1.0000x reference)
#include <cuda_runtime.h>
#include <stdint.h>
#include <math.h>

#define T_LEN 2048
#define ELMO  1024
#define SP_EMB 64
#define HDIM  1024
#define IN0   1088
#define TAGS  50
#define G4    4096
#define JCAP  16
#define CTAS_PER_DIR 64
#define REC_GRID (2 * CTAS_PER_DIR)
#define REC_THREADS 256

#define NREG_P 5                  // rows q=0..4 per warp in registers
#define SMEM_W_ROWS 24            // rows q=5..7 per warp (3 x 8 warps) in SMEM
// smem: sw 24*1024 + sh_h 1024
#define REC_SMEM_FLOATS (SMEM_W_ROWS * HDIM + HDIM)
#define REC_SMEM_BYTES (REC_SMEM_FLOATS * 4)

// ---------------- scratch (static device globals; no allocation) -------------
__device__ float g_embeds[(size_t)T_LEN * IN0];
__device__ float g_xproj[(size_t)T_LEN * 8192];
__device__ float g_h0[(size_t)T_LEN * 2048];
__device__ float g_h1[(size_t)T_LEN * 2048];
__device__ float g_bias[2][8192];
// epoch-tagged h: [layer][buf(2)][dir(2)][1024] of u64 {tag<<32 | h_bits}
__device__ unsigned long long g_hpair[2][4096];
__device__ int g_dummy;

// ---------------- helpers ----------------------------------------------------
__device__ __forceinline__ void fma2(unsigned long long &c, unsigned long long a,
                                     unsigned long long b) {
    asm("fma.rn.f32x2 %0, %1, %2, %3;" : "=l"(c) : "l"(a), "l"(b), "l"(c));
}
__device__ __forceinline__ unsigned long long pack2(float x) {
    unsigned long long r;
    unsigned u = __float_as_uint(x);
    asm("mov.b64 %0, {%1, %1};" : "=l"(r) : "r"(u));
    return r;
}
__device__ __forceinline__ float lo32(unsigned long long v) {
    return __uint_as_float((unsigned)v);
}
__device__ __forceinline__ float hi32(unsigned long long v) {
    return __uint_as_float((unsigned)(v >> 32));
}
__device__ __forceinline__ float sigf(float x) {
    return 1.0f / (1.0f + __expf(-x));
}
__device__ __forceinline__ float tanhfast(float x) {
    float xc = fminf(fmaxf(x, -15.0f), 15.0f);
    float e = __expf(-2.0f * xc);
    return (1.0f - e) / (1.0f + e);
}

// ---------------- fused setup kernel ------------------------------------------
// blocks [0,2048): embed; [2048,2080): bias; [2080,2112): zero g_hpair
__global__ void setup_kernel(const float* __restrict__ sent,
                             const int* __restrict__ tags,
                             const float* __restrict__ emb,
                             const float* __restrict__ bi0, const float* __restrict__ bh0,
                             const float* __restrict__ bi1, const float* __restrict__ bh1) {
    int b = blockIdx.x;
    if (b < T_LEN) {
        float* dst = g_embeds + (size_t)b * IN0;
        const float* s = sent + (size_t)b * ELMO;
        for (int i = threadIdx.x; i < ELMO; i += blockDim.x) dst[i] = s[i];
        const float* e = emb + (size_t)tags[b] * SP_EMB;
        for (int i = threadIdx.x; i < SP_EMB; i += blockDim.x) dst[ELMO + i] = e[i];
    } else if (b < T_LEN + 32) {
        int i = (b - T_LEN) * 256 + threadIdx.x;
        g_bias[0][i] = bi0[i] + bh0[i];
        g_bias[1][i] = bi1[i] + bh1[i];
    } else {
        int i = (b - T_LEN - 32) * 256 + threadIdx.x;
        ((unsigned long long*)g_hpair)[i] = 0ull;   // tag 0, h = 0
    }
}

__global__ void pad_kernel() { if (threadIdx.x == 0) g_dummy = 1; }

// ---------------- SGEMM (NT): C[m][n] = sum_k A[m][k]*B[n][k] + bias[n] -------
__global__ void __launch_bounds__(256, 2)
sgemm_nt(const float* __restrict__ A, const float* __restrict__ B,
         const float* __restrict__ bias, float* __restrict__ C,
         int M, int N, int K) {
    __shared__ float As[2][8][128];
    __shared__ float Bs[2][8][128];

    int tid = threadIdx.x;
    int bm = blockIdx.y * 128;
    int bn = blockIdx.x * 128;
    int lm = tid >> 1;
    int lk = (tid & 1) * 4;
    int ty = tid >> 4;
    int tx = tid & 15;

    const float* Aptr = A + (size_t)(bm + lm) * K + lk;
    const float* Bptr = B + (size_t)(bn + lm) * K + lk;
    bool bvalid = (bn + lm) < N;

    float4 ra = *(const float4*)Aptr;
    float4 rb = bvalid ? *(const float4*)Bptr : make_float4(0.f, 0.f, 0.f, 0.f);
    As[0][lk + 0][lm] = ra.x; As[0][lk + 1][lm] = ra.y;
    As[0][lk + 2][lm] = ra.z; As[0][lk + 3][lm] = ra.w;
    Bs[0][lk + 0][lm] = rb.x; Bs[0][lk + 1][lm] = rb.y;
    Bs[0][lk + 2][lm] = rb.z; Bs[0][lk + 3][lm] = rb.w;
    __syncthreads();

    unsigned long long acc[8][4];
#pragma unroll
    for (int i = 0; i < 8; i++)
#pragma unroll
        for (int j = 0; j < 4; j++) acc[i][j] = 0ull;

    int nk = K >> 3;
    for (int kt = 0; kt < nk; kt++) {
        int buf = kt & 1;
        if (kt + 1 < nk) {
            ra = *(const float4*)(Aptr + (size_t)(kt + 1) * 8);
            rb = bvalid ? *(const float4*)(Bptr + (size_t)(kt + 1) * 8)
                        : make_float4(0.f, 0.f, 0.f, 0.f);
        }
#pragma unroll
        for (int kk = 0; kk < 8; kk++) {
            float4 a0 = *(const float4*)&As[buf][kk][ty * 8];
            float4 a1 = *(const float4*)&As[buf][kk][ty * 8 + 4];
            const unsigned long long* bp =
                (const unsigned long long*)&Bs[buf][kk][tx * 8];
            unsigned long long b0 = bp[0], b1 = bp[1], b2 = bp[2], b3 = bp[3];
            float av[8] = {a0.x, a0.y, a0.z, a0.w, a1.x, a1.y, a1.z, a1.w};
#pragma unroll
            for (int i = 0; i < 8; i++) {
                unsigned long long a2 = pack2(av[i]);
                fma2(acc[i][0], a2, b0);
                fma2(acc[i][1], a2, b1);
                fma2(acc[i][2], a2, b2);
                fma2(acc[i][3], a2, b3);
            }
        }
        if (kt + 1 < nk) {
            int nb = buf ^ 1;
            As[nb][lk + 0][lm] = ra.x; As[nb][lk + 1][lm] = ra.y;
            As[nb][lk + 2][lm] = ra.z; As[nb][lk + 3][lm] = ra.w;
            Bs[nb][lk + 0][lm] = rb.x; Bs[nb][lk + 1][lm] = rb.y;
            Bs[nb][lk + 2][lm] = rb.z; Bs[nb][lk + 3][lm] = rb.w;
            __syncthreads();
        }
    }

#pragma unroll
    for (int i = 0; i < 8; i++) {
        int m = bm + ty * 8 + i;
        float* crow = C + (size_t)m * N;
#pragma unroll
        for (int j2 = 0; j2 < 4; j2++) {
            int n0 = bn + tx * 8 + j2 * 2;
            unsigned long long v = acc[i][j2];
            if (n0 < N)     crow[n0]     = lo32(v) + bias[n0];
            if (n0 + 1 < N) crow[n0 + 1] = hi32(v) + bias[n0 + 1];
        }
    }
}

// ---------------- persistent BiLSTM recurrence (warp-local gates) -------------
// 128 CTAs (64/dir). CTA owns 16 units. Warp w owns units {2w, 2w+1}:
// 8 gate rows, q=2g+p (g=gate, p=unit parity). q=0..4 in registers, q=5..7 in
// SMEM. After warp xor-reduce all 8 sums are in every lane; lanes 0/1 do gate
// math and publish epoch-tagged h {tag,h} via st.release. Readers spin on the
// tags INDEPENDENTLY (no barrier in loop), stage h to SMEM; one block barrier
// per step.
__global__ void __launch_bounds__(REC_THREADS, 1)
lstm_rec(const float* __restrict__ w_hh,          // [2][4096][1024]
         const float* __restrict__ xproj,         // [T][8192]
         float* __restrict__ hout,                // [T][2048]
         unsigned long long* __restrict__ hpair)  // [2][2][1024] this layer
{
    extern __shared__ float smem[];
    float* sw   = smem;                          // 24 * 1024 weight rows
    float* sh_h = smem + SMEM_W_ROWS * HDIM;     // 1024 staged h

    int cta  = blockIdx.x;
    int dir  = cta / CTAS_PER_DIR;
    int cidx = cta % CTAS_PER_DIR;
    int jbase = cidx * JCAP;
    int tid = threadIdx.x;
    int warp = tid >> 5, lane = tid & 31;

    // ---- register-resident rows q = 0..4 (row: gate g=q>>1, unit 2w+(q&1)) --
    unsigned long long wreg[NREG_P][16];
#pragma unroll
    for (int q = 0; q < NREG_P; q++) {
        int g = q >> 1, p = q & 1;
        const unsigned long long* src = (const unsigned long long*)(w_hh +
            ((size_t)dir * G4 + (size_t)g * HDIM + jbase + 2 * warp + p) * HDIM);
#pragma unroll
        for (int m = 0; m < 16; m++) wreg[q][m] = src[lane + 32 * m];
    }
    // ---- SMEM rows q = 5..7 ----
#pragma unroll
    for (int q = NREG_P; q < 8; q++) {
        int g = q >> 1, p = q & 1;
        const unsigned long long* src = (const unsigned long long*)(w_hh +
            ((size_t)dir * G4 + (size_t)g * HDIM + jbase + 2 * warp + p) * HDIM);
        unsigned long long* dst =
            (unsigned long long*)(sw + (size_t)(warp * 3 + q - NREG_P) * HDIM);
#pragma unroll
        for (int m = 0; m < 16; m++) dst[lane + 32 * m] = src[lane + 32 * m];
    }
    __syncthreads();

    float creg = 0.0f;   // cell state, valid in lanes 0/1 (unit 2w+lane)

    for (int s = 0; s < T_LEN; s++) {
        int t_in = dir ? (T_LEN - 1 - s) : s;

        // prefetch x-projection for this warp's two units (lanes 0/1)
        float xq0 = 0.f, xq1 = 0.f, xq2 = 0.f, xq3 = 0.f;
        if (lane < 2) {
            const float* xb = xproj + (size_t)t_in * 8192 + dir * G4
                            + jbase + 2 * warp + lane;
            xq0 = xb[0 * HDIM]; xq1 = xb[1 * HDIM];
            xq2 = xb[2 * HDIM]; xq3 = xb[3 * HDIM];
        }

        // ---- independent spin on this thread's 4 tagged pairs (one 32B sector)
        {
            const unsigned long long* hp =
                hpair + ((size_t)(s & 1) * 2 + dir) * HDIM + tid * 4;
            unsigned tag = (unsigned)s;
            unsigned long long p0, p1, p2, p3;
            for (;;) {
                asm volatile("ld.relaxed.gpu.global.b64 %0, [%1];" : "=l"(p0) : "l"(hp));
                asm volatile("ld.relaxed.gpu.global.b64 %0, [%1];" : "=l"(p1) : "l"(hp + 1));
                asm volatile("ld.relaxed.gpu.global.b64 %0, [%1];" : "=l"(p2) : "l"(hp + 2));
                asm volatile("ld.relaxed.gpu.global.b64 %0, [%1];" : "=l"(p3) : "l"(hp + 3));
                if ((unsigned)(p0 >> 32) == tag && (unsigned)(p1 >> 32) == tag &&
                    (unsigned)(p2 >> 32) == tag && (unsigned)(p3 >> 32) == tag)
                    break;
            }
            sh_h[tid * 4 + 0] = lo32(p0);
            sh_h[tid * 4 + 1] = lo32(p1);
            sh_h[tid * 4 + 2] = lo32(p2);
            sh_h[tid * 4 + 3] = lo32(p3);
        }
        __syncthreads();   // staging complete; the only block barrier per step

        // ---- hu pairs from SMEM (reused across the 8 rows) ----
        unsigned long long hu[16];
        {
            const unsigned long long* shu = (const unsigned long long*)sh_h;
#pragma unroll
            for (int m = 0; m < 16; m++) hu[m] = shu[lane + 32 * m];
        }

        // ---- 8 dot products ----
        float rsum[8];
#pragma unroll
        for (int q = 0; q < NREG_P; q++) {
            unsigned long long a = 0ull;
#pragma unroll
            for (int m = 0; m < 16; m++) fma2(a, wreg[q][m], hu[m]);
            rsum[q] = lo32(a) + hi32(a);
        }
#pragma unroll
        for (int q = NREG_P; q < 8; q++) {
            const unsigned long long* wr = (const unsigned long long*)
                (sw + (size_t)(warp * 3 + q - NREG_P) * HDIM);
            unsigned long long a = 0ull;
#pragma unroll
            for (int m = 0; m < 16; m++) fma2(a, wr[lane + 32 * m], hu[m]);
            rsum[q] = lo32(a) + hi32(a);
        }

        // ---- warp xor-reduce: all lanes end with all 8 sums ----
#pragma unroll
        for (int q = 0; q < 8; q++) {
            float v = rsum[q];
#pragma unroll
            for (int off = 16; off; off >>= 1)
                v += __shfl_xor_sync(0xffffffffu, v, off);
            rsum[q] = v;
        }

        // ---- gate math + publish (lanes 0/1, unit = 2w+lane) ----
        if (lane < 2) {
            float gi = rsum[0 + lane] + xq0;
            float gf = rsum[2 + lane] + xq1;
            float gg = rsum[4 + lane] + xq2;
            float go = rsum[6 + lane] + xq3;
            float c  = sigf(gf) * creg + sigf(gi) * tanhfast(gg);
            float hv = sigf(go) * tanhfast(c);
            creg = c;
            int j = jbase + 2 * warp + lane;
            unsigned long long pv = ((unsigned long long)(unsigned)(s + 1) << 32)
                                  | (unsigned long long)__float_as_uint(hv);
            unsigned long long* hw =
                hpair + ((size_t)((s + 1) & 1) * 2 + dir) * HDIM + j;
            asm volatile("st.release.gpu.global.b64 [%0], %1;"
                         :: "l"(hw), "l"(pv) : "memory");
            hout[(size_t)t_in * 2048 + dir * HDIM + j] = hv;
        }
        // no trailing barrier: a thread can only pass its next spin (and touch
        // sh_h again) after every warp in every CTA has published step s+1,
        // which happens-after all step-s sh_h reads.
    }
}

// ---------------- launcher ----------------------------------------------------
extern "C" void kernel_launch(void* const* d_in, const int* in_sizes, int n_in,
                              void* d_out, int out_size) {
    const float* sentence = (const float*)d_in[0];
    const int*   tags     = (const int*)d_in[1];
    const float* emb      = (const float*)d_in[2];
    const float* w_ih0    = (const float*)d_in[3];
    const float* w_hh0    = (const float*)d_in[4];
    const float* b_ih0    = (const float*)d_in[5];
    const float* b_hh0    = (const float*)d_in[6];
    const float* w_ih1    = (const float*)d_in[7];
    const float* w_hh1    = (const float*)d_in[8];
    const float* b_ih1    = (const float*)d_in[9];
    const float* b_hh1    = (const float*)d_in[10];
    const float* w_out    = (const float*)d_in[11];
    const float* b_out    = (const float*)d_in[12];
    float* out = (float*)d_out;

    cudaFuncSetAttribute(lstm_rec, cudaFuncAttributeMaxDynamicSharedMemorySize,
                         REC_SMEM_BYTES);

    float *p_embeds, *p_xproj, *p_h0, *p_h1, *p_bias;
    unsigned long long* p_hpair;
    cudaGetSymbolAddress((void**)&p_embeds, g_embeds);
    cudaGetSymbolAddress((void**)&p_xproj,  g_xproj);
    cudaGetSymbolAddress((void**)&p_h0,     g_h0);
    cudaGetSymbolAddress((void**)&p_h1,     g_h1);
    cudaGetSymbolAddress((void**)&p_bias,   g_bias);
    cudaGetSymbolAddress((void**)&p_hpair,  g_hpair);

    // launch order: ncu reliably captures launch #4 -> lstm_rec(L0)
    setup_kernel<<<T_LEN + 64, 256>>>(sentence, tags, emb,                   // 1
                                      b_ih0, b_hh0, b_ih1, b_hh1);
    pad_kernel<<<1, 32>>>();                                                 // 2
    sgemm_nt<<<dim3(64, 16), 256>>>(p_embeds, w_ih0, p_bias,                 // 3
                                    p_xproj, T_LEN, 8192, IN0);
    lstm_rec<<<REC_GRID, REC_THREADS, REC_SMEM_BYTES>>>(                     // 4
        w_hh0, p_xproj, p_h0, p_hpair);
    sgemm_nt<<<dim3(64, 16), 256>>>(p_h0, w_ih1, p_bias + 8192,              // 5
                                    p_xproj, T_LEN, 8192, 2048);
    lstm_rec<<<REC_GRID, REC_THREADS, REC_SMEM_BYTES>>>(                     // 6
        w_hh1, p_xproj, p_h1, p_hpair + 4096);
    sgemm_nt<<<dim3(1, 16), 256>>>(p_h1, w_out, b_out, out,                  // 7
                                   T_LEN, TAGS, 2048);
}

// round 17
// speedup vs baseline: 1.1318x; 1.1318x over previous
#include <cuda_runtime.h>
#include <stdint.h>
#include <math.h>

#define T_LEN 2048
#define ELMO  1024
#define SP_EMB 64
#define HDIM  1024
#define IN0   1088
#define TAGS  50
#define G4    4096
#define JCAP  16
#define CTAS_PER_DIR 64
#define REC_GRID (2 * CTAS_PER_DIR)
#define REC_THREADS 256

#define NREG_P 5                  // rows q=0..4 per warp in registers
#define SMEM_W_ROWS 24            // rows q=5..7 per warp (3 x 8 warps) in SMEM
// smem: sw 24*1024 + sh_h 1024
#define REC_SMEM_FLOATS (SMEM_W_ROWS * HDIM + HDIM)
#define REC_SMEM_BYTES (REC_SMEM_FLOATS * 4)

// ---------------- scratch (static device globals; no allocation) -------------
__device__ float g_embeds[(size_t)T_LEN * IN0];
__device__ float g_xproj[(size_t)T_LEN * 8192];
__device__ float g_h0[(size_t)T_LEN * 2048];
__device__ float g_h1[(size_t)T_LEN * 2048];
__device__ float g_bias[2][8192];
__device__ float g_hbuf[2][2][2][HDIM];   // [layer][buf][dir][H] plain h
__device__ unsigned g_barc[2][2];         // [layer][dir] step counters
__device__ int g_dummy;

// ---------------- helpers ----------------------------------------------------
__device__ __forceinline__ void fma2(unsigned long long &c, unsigned long long a,
                                     unsigned long long b) {
    asm("fma.rn.f32x2 %0, %1, %2, %3;" : "=l"(c) : "l"(a), "l"(b), "l"(c));
}
__device__ __forceinline__ unsigned long long pack2(float x) {
    unsigned long long r;
    unsigned u = __float_as_uint(x);
    asm("mov.b64 %0, {%1, %1};" : "=l"(r) : "r"(u));
    return r;
}
__device__ __forceinline__ float lo32(unsigned long long v) {
    return __uint_as_float((unsigned)v);
}
__device__ __forceinline__ float hi32(unsigned long long v) {
    return __uint_as_float((unsigned)(v >> 32));
}
__device__ __forceinline__ float sigf(float x) {
    return 1.0f / (1.0f + __expf(-x));
}
__device__ __forceinline__ float tanhfast(float x) {
    float xc = fminf(fmaxf(x, -15.0f), 15.0f);
    float e = __expf(-2.0f * xc);
    return (1.0f - e) / (1.0f + e);
}

// ---------------- fused setup kernel ------------------------------------------
// blocks [0,2048): embed; [2048,2080): bias; [2080,2112): zero hbuf+counters
__global__ void setup_kernel(const float* __restrict__ sent,
                             const int* __restrict__ tags,
                             const float* __restrict__ emb,
                             const float* __restrict__ bi0, const float* __restrict__ bh0,
                             const float* __restrict__ bi1, const float* __restrict__ bh1) {
    int b = blockIdx.x;
    if (b < T_LEN) {
        float* dst = g_embeds + (size_t)b * IN0;
        const float* s = sent + (size_t)b * ELMO;
        for (int i = threadIdx.x; i < ELMO; i += blockDim.x) dst[i] = s[i];
        const float* e = emb + (size_t)tags[b] * SP_EMB;
        for (int i = threadIdx.x; i < SP_EMB; i += blockDim.x) dst[ELMO + i] = e[i];
    } else if (b < T_LEN + 32) {
        int i = (b - T_LEN) * 256 + threadIdx.x;
        g_bias[0][i] = bi0[i] + bh0[i];
        g_bias[1][i] = bi1[i] + bh1[i];
    } else {
        int i = (b - T_LEN - 32) * 256 + threadIdx.x;
        ((float*)g_hbuf)[i] = 0.0f;      // 8192 floats = both layers' h state
        if (i < 4) ((unsigned*)g_barc)[i] = 0u;
    }
}

__global__ void pad_kernel() { if (threadIdx.x == 0) g_dummy = 1; }

// ---------------- SGEMM (NT): C[m][n] = sum_k A[m][k]*B[n][k] + bias[n] -------
__global__ void __launch_bounds__(256, 2)
sgemm_nt(const float* __restrict__ A, const float* __restrict__ B,
         const float* __restrict__ bias, float* __restrict__ C,
         int M, int N, int K) {
    __shared__ float As[2][8][128];
    __shared__ float Bs[2][8][128];

    int tid = threadIdx.x;
    int bm = blockIdx.y * 128;
    int bn = blockIdx.x * 128;
    int lm = tid >> 1;
    int lk = (tid & 1) * 4;
    int ty = tid >> 4;
    int tx = tid & 15;

    const float* Aptr = A + (size_t)(bm + lm) * K + lk;
    const float* Bptr = B + (size_t)(bn + lm) * K + lk;
    bool bvalid = (bn + lm) < N;

    float4 ra = *(const float4*)Aptr;
    float4 rb = bvalid ? *(const float4*)Bptr : make_float4(0.f, 0.f, 0.f, 0.f);
    As[0][lk + 0][lm] = ra.x; As[0][lk + 1][lm] = ra.y;
    As[0][lk + 2][lm] = ra.z; As[0][lk + 3][lm] = ra.w;
    Bs[0][lk + 0][lm] = rb.x; Bs[0][lk + 1][lm] = rb.y;
    Bs[0][lk + 2][lm] = rb.z; Bs[0][lk + 3][lm] = rb.w;
    __syncthreads();

    unsigned long long acc[8][4];
#pragma unroll
    for (int i = 0; i < 8; i++)
#pragma unroll
        for (int j = 0; j < 4; j++) acc[i][j] = 0ull;

    int nk = K >> 3;
    for (int kt = 0; kt < nk; kt++) {
        int buf = kt & 1;
        if (kt + 1 < nk) {
            ra = *(const float4*)(Aptr + (size_t)(kt + 1) * 8);
            rb = bvalid ? *(const float4*)(Bptr + (size_t)(kt + 1) * 8)
                        : make_float4(0.f, 0.f, 0.f, 0.f);
        }
#pragma unroll
        for (int kk = 0; kk < 8; kk++) {
            float4 a0 = *(const float4*)&As[buf][kk][ty * 8];
            float4 a1 = *(const float4*)&As[buf][kk][ty * 8 + 4];
            const unsigned long long* bp =
                (const unsigned long long*)&Bs[buf][kk][tx * 8];
            unsigned long long b0 = bp[0], b1 = bp[1], b2 = bp[2], b3 = bp[3];
            float av[8] = {a0.x, a0.y, a0.z, a0.w, a1.x, a1.y, a1.z, a1.w};
#pragma unroll
            for (int i = 0; i < 8; i++) {
                unsigned long long a2 = pack2(av[i]);
                fma2(acc[i][0], a2, b0);
                fma2(acc[i][1], a2, b1);
                fma2(acc[i][2], a2, b2);
                fma2(acc[i][3], a2, b3);
            }
        }
        if (kt + 1 < nk) {
            int nb = buf ^ 1;
            As[nb][lk + 0][lm] = ra.x; As[nb][lk + 1][lm] = ra.y;
            As[nb][lk + 2][lm] = ra.z; As[nb][lk + 3][lm] = ra.w;
            Bs[nb][lk + 0][lm] = rb.x; Bs[nb][lk + 1][lm] = rb.y;
            Bs[nb][lk + 2][lm] = rb.z; Bs[nb][lk + 3][lm] = rb.w;
            __syncthreads();
        }
    }

#pragma unroll
    for (int i = 0; i < 8; i++) {
        int m = bm + ty * 8 + i;
        float* crow = C + (size_t)m * N;
#pragma unroll
        for (int j2 = 0; j2 < 4; j2++) {
            int n0 = bn + tx * 8 + j2 * 2;
            unsigned long long v = acc[i][j2];
            if (n0 < N)     crow[n0]     = lo32(v) + bias[n0];
            if (n0 + 1 < N) crow[n0 + 1] = hi32(v) + bias[n0 + 1];
        }
    }
}

// ---------------- persistent BiLSTM recurrence --------------------------------
// 128 CTAs (64/dir). CTA owns 16 units; warp w owns units {2w, 2w+1} -> 8 gate
// rows (q=2g+p). q=0..4 in registers, q=5..7 in SMEM. Warp xor-reduce leaves
// all 8 gate sums in every lane; lanes 0/1 do gate math, publish plain h to a
// double-buffered global vector. Sync = proven counter barrier: red.release
// arrive by tid0 + acquire spin; h staged once into SMEM per CTA (4KB
// coalesced) at step start.
__global__ void __launch_bounds__(REC_THREADS, 1)
lstm_rec(const float* __restrict__ w_hh,   // [2][4096][1024]
         const float* __restrict__ xproj,  // [T][8192]
         float* __restrict__ hout,         // [T][2048]
         float* __restrict__ hbuf,         // [2][2][1024] this layer
         unsigned* __restrict__ barc)      // [2] this layer
{
    extern __shared__ float smem[];
    float* sw   = smem;                          // 24 * 1024 weight rows
    float* sh_h = smem + SMEM_W_ROWS * HDIM;     // 1024 staged h

    int cta  = blockIdx.x;
    int dir  = cta / CTAS_PER_DIR;
    int cidx = cta % CTAS_PER_DIR;
    int jbase = cidx * JCAP;
    int tid = threadIdx.x;
    int warp = tid >> 5, lane = tid & 31;

    // ---- register-resident rows q = 0..4 (gate g=q>>1, unit 2w+(q&1)) ----
    unsigned long long wreg[NREG_P][16];
#pragma unroll
    for (int q = 0; q < NREG_P; q++) {
        int g = q >> 1, p = q & 1;
        const unsigned long long* src = (const unsigned long long*)(w_hh +
            ((size_t)dir * G4 + (size_t)g * HDIM + jbase + 2 * warp + p) * HDIM);
#pragma unroll
        for (int m = 0; m < 16; m++) wreg[q][m] = src[lane + 32 * m];
    }
    // ---- SMEM rows q = 5..7 ----
#pragma unroll
    for (int q = NREG_P; q < 8; q++) {
        int g = q >> 1, p = q & 1;
        const unsigned long long* src = (const unsigned long long*)(w_hh +
            ((size_t)dir * G4 + (size_t)g * HDIM + jbase + 2 * warp + p) * HDIM);
        unsigned long long* dst =
            (unsigned long long*)(sw + (size_t)(warp * 3 + q - NREG_P) * HDIM);
#pragma unroll
        for (int m = 0; m < 16; m++) dst[lane + 32 * m] = src[lane + 32 * m];
    }
    __syncthreads();

    unsigned* bar = &barc[dir];
    float creg = 0.0f;   // cell state, lanes 0/1 (unit 2w+lane)

    for (int s = 0; s < T_LEN; s++) {
        int t_in = dir ? (T_LEN - 1 - s) : s;

        // prefetch x-projection for this warp's two units (lanes 0/1)
        float xq0 = 0.f, xq1 = 0.f, xq2 = 0.f, xq3 = 0.f;
        if (lane < 2) {
            const float* xb = xproj + (size_t)t_in * 8192 + dir * G4
                            + jbase + 2 * warp + lane;
            xq0 = xb[0 * HDIM]; xq1 = xb[1 * HDIM];
            xq2 = xb[2 * HDIM]; xq3 = xb[3 * HDIM];
        }

        // ---- stage h_s into SMEM: one coalesced 4KB load per CTA ----
        {
            const float4* hp = (const float4*)
                (hbuf + ((size_t)(s & 1) * 2 + dir) * HDIM);
            ((float4*)sh_h)[tid] = hp[tid];
        }
        __syncthreads();

        // ---- hu pairs from SMEM (reused across the 8 rows) ----
        unsigned long long hu[16];
        {
            const unsigned long long* shu = (const unsigned long long*)sh_h;
#pragma unroll
            for (int m = 0; m < 16; m++) hu[m] = shu[lane + 32 * m];
        }

        // ---- 8 dot products ----
        float rsum[8];
#pragma unroll
        for (int q = 0; q < NREG_P; q++) {
            unsigned long long a = 0ull;
#pragma unroll
            for (int m = 0; m < 16; m++) fma2(a, wreg[q][m], hu[m]);
            rsum[q] = lo32(a) + hi32(a);
        }
#pragma unroll
        for (int q = NREG_P; q < 8; q++) {
            const unsigned long long* wr = (const unsigned long long*)
                (sw + (size_t)(warp * 3 + q - NREG_P) * HDIM);
            unsigned long long a = 0ull;
#pragma unroll
            for (int m = 0; m < 16; m++) fma2(a, wr[lane + 32 * m], hu[m]);
            rsum[q] = lo32(a) + hi32(a);
        }

        // ---- warp xor-reduce: all lanes end with all 8 sums ----
#pragma unroll
        for (int q = 0; q < 8; q++) {
            float v = rsum[q];
#pragma unroll
            for (int off = 16; off; off >>= 1)
                v += __shfl_xor_sync(0xffffffffu, v, off);
            rsum[q] = v;
        }

        // ---- gate math + publish h_{s+1} (lanes 0/1) ----
        float hv = 0.0f;
        int j = jbase + 2 * warp + lane;
        if (lane < 2) {
            float gi = rsum[0 + lane] + xq0;
            float gf = rsum[2 + lane] + xq1;
            float gg = rsum[4 + lane] + xq2;
            float go = rsum[6 + lane] + xq3;
            float c  = sigf(gf) * creg + sigf(gi) * tanhfast(gg);
            hv = sigf(go) * tanhfast(c);
            creg = c;
            hbuf[((size_t)((s + 1) & 1) * 2 + dir) * HDIM + j] = hv;
        }

        // ---- counter barrier: release-arrive, overlap hout store, spin ----
        if (tid == 0) {
            asm volatile("red.release.gpu.global.add.u32 [%0], %1;"
                         :: "l"(bar), "r"(1u) : "memory");
        }
        if (lane < 2)
            hout[(size_t)t_in * 2048 + dir * HDIM + j] = hv;
        if (tid == 0) {
            unsigned target = (unsigned)(s + 1) * CTAS_PER_DIR;
            unsigned v;
            do {
                asm volatile("ld.global.acquire.gpu.u32 %0, [%1];"
                             : "=r"(v) : "l"(bar));
            } while (v < target);
        }
        __syncthreads();
    }
}

// ---------------- launcher ----------------------------------------------------
extern "C" void kernel_launch(void* const* d_in, const int* in_sizes, int n_in,
                              void* d_out, int out_size) {
    const float* sentence = (const float*)d_in[0];
    const int*   tags     = (const int*)d_in[1];
    const float* emb      = (const float*)d_in[2];
    const float* w_ih0    = (const float*)d_in[3];
    const float* w_hh0    = (const float*)d_in[4];
    const float* b_ih0    = (const float*)d_in[5];
    const float* b_hh0    = (const float*)d_in[6];
    const float* w_ih1    = (const float*)d_in[7];
    const float* w_hh1    = (const float*)d_in[8];
    const float* b_ih1    = (const float*)d_in[9];
    const float* b_hh1    = (const float*)d_in[10];
    const float* w_out    = (const float*)d_in[11];
    const float* b_out    = (const float*)d_in[12];
    float* out = (float*)d_out;

    cudaFuncSetAttribute(lstm_rec, cudaFuncAttributeMaxDynamicSharedMemorySize,
                         REC_SMEM_BYTES);

    float *p_embeds, *p_xproj, *p_h0, *p_h1, *p_bias, *p_hb;
    unsigned* p_bar;
    cudaGetSymbolAddress((void**)&p_embeds, g_embeds);
    cudaGetSymbolAddress((void**)&p_xproj,  g_xproj);
    cudaGetSymbolAddress((void**)&p_h0,     g_h0);
    cudaGetSymbolAddress((void**)&p_h1,     g_h1);
    cudaGetSymbolAddress((void**)&p_bias,   g_bias);
    cudaGetSymbolAddress((void**)&p_hb,     g_hbuf);
    cudaGetSymbolAddress((void**)&p_bar,    g_barc);

    // launch order: ncu reliably captures launch #4 -> lstm_rec(L0)
    setup_kernel<<<T_LEN + 64, 256>>>(sentence, tags, emb,                   // 1
                                      b_ih0, b_hh0, b_ih1, b_hh1);
    pad_kernel<<<1, 32>>>();                                                 // 2
    sgemm_nt<<<dim3(64, 16), 256>>>(p_embeds, w_ih0, p_bias,                 // 3
                                    p_xproj, T_LEN, 8192, IN0);
    lstm_rec<<<REC_GRID, REC_THREADS, REC_SMEM_BYTES>>>(                     // 4
        w_hh0, p_xproj, p_h0, p_hb, p_bar);
    sgemm_nt<<<dim3(64, 16), 256>>>(p_h0, w_ih1, p_bias + 8192,              // 5
                                    p_xproj, T_LEN, 8192, 2048);
    lstm_rec<<<REC_GRID, REC_THREADS, REC_SMEM_BYTES>>>(                     // 6
        w_hh1, p_xproj, p_h1, p_hb + 4 * HDIM, p_bar + 2);   // FIX: layer stride = 4*HDIM
    sgemm_nt<<<dim3(1, 16), 256>>>(p_h1, w_out, b_out, out,                  // 7
                                   T_LEN, TAGS, 2048);
}